// round 2
// baseline (speedup 1.0000x reference)
#include <cuda_runtime.h>
#include <cstdint>

#define V     50000
#define E     800000
#define BATCH 4
#define CIN   64
#define COUT  128
#define KORD  4
#define F     256                  // BATCH*CIN feature width per vertex
#define PANEL ((size_t)V * F)      // floats per Chebyshev feature buffer

// Scratch: 4 Chebyshev feature panels (V x 256 fp32 each, b-major inner) + CSR row ptr
__device__ float g_feat[KORD][V * F];
__device__ int   g_rowptr[V + 1];

// ---------------------------------------------------------------------------
// 1) Transpose x (B, Cin, V) -> feat0 (V, B*Cin)   [row-major, b-major inner]
// ---------------------------------------------------------------------------
__global__ void transpose_kernel(const float* __restrict__ x) {
    __shared__ float tile[32][33];
    int v0 = blockIdx.x * 32;
    int c0 = blockIdx.y * 32;      // c = b*CIN + i in [0, 256)
    int tx = threadIdx.x, ty = threadIdx.y;
    int v = v0 + tx;
    if (v < V) tile[ty][tx] = x[(size_t)(c0 + ty) * V + v];
    __syncthreads();
    int vv = v0 + ty;
    if (vv < V) g_feat[0][(size_t)vv * F + c0 + tx] = tile[tx][ty];
}

// ---------------------------------------------------------------------------
// 2) row_ptr from sorted COO rows (binary search per row boundary)
// ---------------------------------------------------------------------------
__global__ void rowptr_kernel(const int* __restrict__ rows) {
    int r = blockIdx.x * blockDim.x + threadIdx.x;
    if (r > V) return;
    int lo = 0, hi = E;
    while (lo < hi) {
        int mid = (lo + hi) >> 1;
        if (rows[mid] < r) lo = mid + 1; else hi = mid;
    }
    g_rowptr[r] = lo;
}

// ---------------------------------------------------------------------------
// 3) SpMM: one warp per output row, 256-wide features (8 floats per lane).
//    cheb==0 : out = L @ in
//    cheb==1 : out = 2 * (L @ in) - prev
// ---------------------------------------------------------------------------
__global__ void spmm_kernel(const int* __restrict__ cols,
                            const float* __restrict__ vals,
                            int in_idx, int out_idx, int prev_idx, int cheb) {
    int r    = blockIdx.x * 8 + (threadIdx.x >> 5);   // grid = V/8 exactly
    int lane = threadIdx.x & 31;
    const float4* xin  = (const float4*)&g_feat[in_idx][0];
    float4*       xout = (float4*)&g_feat[out_idx][0];

    int e  = g_rowptr[r];
    int e1 = g_rowptr[r + 1];

    float4 a0 = make_float4(0.f, 0.f, 0.f, 0.f);
    float4 a1 = make_float4(0.f, 0.f, 0.f, 0.f);

    int   c = 0;
    float w = 0.f;
    if (e < e1) { c = __ldg(cols + e); w = __ldg(vals + e); }

    while (e < e1) {
        const float4* s = xin + (size_t)c * 64;
        float4 p = s[lane];
        float4 q = s[lane + 32];
        ++e;
        int   cn = 0;
        float wn = 0.f;
        if (e < e1) { cn = __ldg(cols + e); wn = __ldg(vals + e); }
        a0.x += w * p.x; a0.y += w * p.y; a0.z += w * p.z; a0.w += w * p.w;
        a1.x += w * q.x; a1.y += w * q.y; a1.z += w * q.z; a1.w += w * q.w;
        c = cn; w = wn;
    }

    size_t o = (size_t)r * 64;
    if (cheb) {
        const float4* xprev = (const float4*)&g_feat[prev_idx][0];
        float4 p0 = xprev[o + lane];
        float4 p1 = xprev[o + lane + 32];
        a0.x = 2.f * a0.x - p0.x; a0.y = 2.f * a0.y - p0.y;
        a0.z = 2.f * a0.z - p0.z; a0.w = 2.f * a0.w - p0.w;
        a1.x = 2.f * a1.x - p1.x; a1.y = 2.f * a1.y - p1.y;
        a1.z = 2.f * a1.z - p1.z; a1.w = 2.f * a1.w - p1.w;
    }
    xout[o + lane]      = a0;
    xout[o + lane + 32] = a1;
}

// ---------------------------------------------------------------------------
// 4) tf32 tensor-core GEMM:
//    C[r][o] = sum_{p,i} feat_p[r][i] * W[p][i][o] + bias[o],  r = v*4 + b
//    M = 200000, K = 4 x 64 panels, N = 128.
//    Block: 64 rows x 128 cols, 256 threads (8 warps: 4 m-warps x 2 n-warps).
//    Output scatter to (B, COUT, V).
// ---------------------------------------------------------------------------
__device__ __forceinline__ uint32_t f2tf32(float x) {
    uint32_t y;
    asm("cvt.rna.tf32.f32 %0, %1;" : "=r"(y) : "f"(x));
    return y;
}

__device__ __forceinline__ void mma_tf32(float c[4],
                                         uint32_t a0, uint32_t a1, uint32_t a2, uint32_t a3,
                                         uint32_t b0, uint32_t b1) {
    asm volatile(
        "mma.sync.aligned.m16n8k8.row.col.f32.tf32.tf32.f32 "
        "{%0,%1,%2,%3}, {%4,%5,%6,%7}, {%8,%9}, {%0,%1,%2,%3};"
        : "+f"(c[0]), "+f"(c[1]), "+f"(c[2]), "+f"(c[3])
        : "r"(a0), "r"(a1), "r"(a2), "r"(a3), "r"(b0), "r"(b1));
}

#define AS_STRIDE 68    // 64 + 4  -> a-frag banks: (4*row + tg) all distinct
#define WP_STRIDE 136   // 128 + 8 -> b-frag banks: (8*tg + g) all distinct
#define GEMM_SMEM ((64 * AS_STRIDE + 64 * WP_STRIDE) * 4)   // 52224 bytes

__global__ void gemm_kernel(const float* __restrict__ w,
                            const float* __restrict__ bias,
                            float* __restrict__ out) {
    extern __shared__ float smem[];
    float* As = smem;                    // [64][AS_STRIDE]
    float* Wp = smem + 64 * AS_STRIDE;   // [64][WP_STRIDE]

    int tid  = threadIdx.x;
    int wid  = tid >> 5, lane = tid & 31;
    int wm   = wid & 3;        // m-warp: rows wm*16 .. wm*16+15
    int wn   = wid >> 2;       // n-warp: cols wn*64 .. wn*64+63
    int m0   = blockIdx.x * 64;
    int g    = lane >> 2;      // 0..7
    int tg   = lane & 3;       // 0..3

    float acc[8][4];
    #pragma unroll
    for (int nt = 0; nt < 8; ++nt)
        #pragma unroll
        for (int j = 0; j < 4; ++j) acc[nt][j] = 0.f;

    for (int p = 0; p < KORD; ++p) {
        const float* Ap = &g_feat[p][0];
        // Load A tile: 64 rows x 64 floats (1024 float4, 4 per thread)
        #pragma unroll
        for (int i = 0; i < 4; ++i) {
            int idx  = i * 256 + tid;
            int row  = idx >> 4;
            int col4 = (idx & 15) << 2;
            float4 t = *(const float4*)(Ap + (size_t)(m0 + row) * 64 + col4);
            float* d = As + row * AS_STRIDE + col4;
            d[0] = __uint_as_float(f2tf32(t.x));
            d[1] = __uint_as_float(f2tf32(t.y));
            d[2] = __uint_as_float(f2tf32(t.z));
            d[3] = __uint_as_float(f2tf32(t.w));
        }
        // Load W panel: 64 x 128 floats (2048 float4, 8 per thread)
        const float* wp = w + p * (CIN * COUT);
        #pragma unroll
        for (int i = 0; i < 8; ++i) {
            int idx  = i * 256 + tid;
            int row  = idx >> 5;
            int col4 = (idx & 31) << 2;
            float4 t = *(const float4*)(wp + row * COUT + col4);
            float* d = Wp + row * WP_STRIDE + col4;
            d[0] = __uint_as_float(f2tf32(t.x));
            d[1] = __uint_as_float(f2tf32(t.y));
            d[2] = __uint_as_float(f2tf32(t.z));
            d[3] = __uint_as_float(f2tf32(t.w));
        }
        __syncthreads();

        #pragma unroll
        for (int ks = 0; ks < 8; ++ks) {
            int kb = ks * 8;
            const float* ar  = As + (wm * 16 + g) * AS_STRIDE + kb;
            const float* ar8 = ar + 8 * AS_STRIDE;
            uint32_t a0 = __float_as_uint(ar[tg]);
            uint32_t a1 = __float_as_uint(ar8[tg]);
            uint32_t a2 = __float_as_uint(ar[tg + 4]);
            uint32_t a3 = __float_as_uint(ar8[tg + 4]);
            #pragma unroll
            for (int nt = 0; nt < 8; ++nt) {
                int cb = wn * 64 + nt * 8;
                uint32_t b0 = __float_as_uint(Wp[(kb + tg)     * WP_STRIDE + cb + g]);
                uint32_t b1 = __float_as_uint(Wp[(kb + tg + 4) * WP_STRIDE + cb + g]);
                mma_tf32(acc[nt], a0, a1, a2, a3, b0, b1);
            }
        }
        __syncthreads();
    }

    // Epilogue: add bias, scatter to out[b][o][v], r = v*4 + b
    int r0 = m0 + wm * 16 + g;
    int r1 = r0 + 8;
    size_t v0 = (size_t)(r0 >> 2), b0i = (size_t)(r0 & 3);
    size_t v1 = (size_t)(r1 >> 2), b1i = (size_t)(r1 & 3);
    #pragma unroll
    for (int nt = 0; nt < 8; ++nt) {
        int o0 = wn * 64 + nt * 8 + 2 * tg;
        float bv0 = __ldg(bias + o0);
        float bv1 = __ldg(bias + o0 + 1);
        out[b0i * ((size_t)COUT * V) + (size_t)o0       * V + v0] = acc[nt][0] + bv0;
        out[b0i * ((size_t)COUT * V) + (size_t)(o0 + 1) * V + v0] = acc[nt][1] + bv1;
        out[b1i * ((size_t)COUT * V) + (size_t)o0       * V + v1] = acc[nt][2] + bv0;
        out[b1i * ((size_t)COUT * V) + (size_t)(o0 + 1) * V + v1] = acc[nt][3] + bv1;
    }
}

// ---------------------------------------------------------------------------
extern "C" void kernel_launch(void* const* d_in, const int* in_sizes, int n_in,
                              void* d_out, int out_size) {
    const float* x    = (const float*)d_in[0];
    const int*   rows = (const int*)  d_in[1];
    const int*   cols = (const int*)  d_in[2];
    const float* vals = (const float*)d_in[3];
    const float* w    = (const float*)d_in[4];
    const float* bias = (const float*)d_in[5];
    float*       out  = (float*)d_out;

    (void)in_sizes; (void)n_in; (void)out_size;

    cudaFuncSetAttribute(gemm_kernel,
                         cudaFuncAttributeMaxDynamicSharedMemorySize, GEMM_SMEM);

    // feat0 = x^T
    transpose_kernel<<<dim3((V + 31) / 32, F / 32), dim3(32, 32)>>>(x);
    // CSR row pointers
    rowptr_kernel<<<(V + 1 + 255) / 256, 256>>>(rows);
    // Chebyshev recurrence
    spmm_kernel<<<V / 8, 256>>>(cols, vals, 0, 1, 0, 0);  // x1 = L x0
    spmm_kernel<<<V / 8, 256>>>(cols, vals, 1, 2, 0, 1);  // x2 = 2 L x1 - x0
    spmm_kernel<<<V / 8, 256>>>(cols, vals, 2, 3, 1, 1);  // x3 = 2 L x2 - x1
    // Fused contraction over all 4 panels + bias + output transpose
    gemm_kernel<<<(V * BATCH) / 64, 256, GEMM_SMEM>>>(w, bias, out);
}

// round 8
// speedup vs baseline: 2.3513x; 2.3513x over previous
#include <cuda_runtime.h>
#include <cuda_fp16.h>
#include <cstdint>

#define V     50000
#define E     800000
#define BATCH 4
#define CIN   64
#define COUT  128
#define KORD  4

// Feature panels: [r = v*4+b][i 0..63] as half  (layout == [v][c=b*64+i])
__device__ __align__(16) __half g_feat[KORD][(size_t)V * BATCH * CIN];
// W transposed to [p][o][i] as half
__device__ __align__(16) __half g_wT[KORD * COUT * CIN];
__device__ int g_rowptr[V + 1];

// ---------------------------------------------------------------------------
// 1) Transpose x (B, Cin, V) -> feat0[v*256 + c] (half)
// ---------------------------------------------------------------------------
__global__ void transpose_kernel(const float* __restrict__ x) {
    __shared__ float tile[32][33];
    int v0 = blockIdx.x * 32;
    int c0 = blockIdx.y * 32;
    int tx = threadIdx.x, ty = threadIdx.y;
    int v = v0 + tx;
    if (v < V) tile[ty][tx] = x[(size_t)(c0 + ty) * V + v];
    __syncthreads();
    int vv = v0 + ty;
    if (vv < V)
        g_feat[0][(size_t)vv * 256 + c0 + tx] = __float2half_rn(tile[tx][ty]);
}

// ---------------------------------------------------------------------------
// 2) row_ptr from sorted COO rows
// ---------------------------------------------------------------------------
__global__ void rowptr_kernel(const int* __restrict__ rows) {
    int r = blockIdx.x * blockDim.x + threadIdx.x;
    if (r > V) return;
    int lo = 0, hi = E;
    while (lo < hi) {
        int mid = (lo + hi) >> 1;
        if (rows[mid] < r) lo = mid + 1; else hi = mid;
    }
    g_rowptr[r] = lo;
}

// ---------------------------------------------------------------------------
// 2b) W (K, Cin, Cout) fp32 -> g_wT (K, Cout, Cin) fp16
// ---------------------------------------------------------------------------
__global__ void wconvert_kernel(const float* __restrict__ w) {
    int n = blockIdx.x * blockDim.x + threadIdx.x;   // < K*COUT*CIN = 32768
    int p = n >> 13;
    int rem = n & 8191;
    int o = rem >> 6;
    int i = rem & 63;
    g_wT[n] = __float2half_rn(w[p * (CIN * COUT) + i * COUT + o]);
}

// ---------------------------------------------------------------------------
// 3) SpMM on fp16 panels: one warp per vertex row (256 halfs = 512B/row).
//    Each lane owns 8 halfs (one uint4). fp32 accumulation.
//    4-edge unrolled gather for MLP on the L2-hit path.
//    cheb==0: out = L@in      cheb==1: out = 2*(L@in) - prev
// ---------------------------------------------------------------------------
__device__ __forceinline__ void acc_edge(float acc[8], uint4 t, float w) {
    const half2* h = (const half2*)&t;
    #pragma unroll
    for (int j = 0; j < 4; ++j) {
        float2 f = __half22float2(h[j]);
        acc[2*j]   += w * f.x;
        acc[2*j+1] += w * f.y;
    }
}

__global__ void spmm_kernel(const int* __restrict__ cols,
                            const float* __restrict__ vals,
                            int in_idx, int out_idx, int prev_idx, int cheb) {
    int r    = blockIdx.x * 8 + (threadIdx.x >> 5);
    int lane = threadIdx.x & 31;
    const uint4* xin  = (const uint4*)&g_feat[in_idx][0];   // 32 uint4 per row
    uint4*       xout = (uint4*)&g_feat[out_idx][0];

    int e  = g_rowptr[r];
    int e1 = g_rowptr[r + 1];

    float acc[8];
    #pragma unroll
    for (int j = 0; j < 8; ++j) acc[j] = 0.f;

    // 4-edge unrolled main loop: 4 independent gathers in flight
    while (e + 4 <= e1) {
        int   c0 = __ldg(cols + e),     c1 = __ldg(cols + e + 1);
        int   c2 = __ldg(cols + e + 2), c3 = __ldg(cols + e + 3);
        float w0 = __ldg(vals + e),     w1 = __ldg(vals + e + 1);
        float w2 = __ldg(vals + e + 2), w3 = __ldg(vals + e + 3);
        uint4 t0 = xin[(size_t)c0 * 32 + lane];
        uint4 t1 = xin[(size_t)c1 * 32 + lane];
        uint4 t2 = xin[(size_t)c2 * 32 + lane];
        uint4 t3 = xin[(size_t)c3 * 32 + lane];
        acc_edge(acc, t0, w0);
        acc_edge(acc, t1, w1);
        acc_edge(acc, t2, w2);
        acc_edge(acc, t3, w3);
        e += 4;
    }
    while (e < e1) {
        int   c = __ldg(cols + e);
        float w = __ldg(vals + e);
        uint4 t = xin[(size_t)c * 32 + lane];
        acc_edge(acc, t, w);
        ++e;
    }

    size_t o = (size_t)r * 32 + lane;
    if (cheb) {
        uint4 pv = ((const uint4*)&g_feat[prev_idx][0])[o];
        const half2* h = (const half2*)&pv;
        #pragma unroll
        for (int j = 0; j < 4; ++j) {
            float2 f = __half22float2(h[j]);
            acc[2*j]   = 2.f * acc[2*j]   - f.x;
            acc[2*j+1] = 2.f * acc[2*j+1] - f.y;
        }
    }
    uint4 res;
    half2* rh = (half2*)&res;
    #pragma unroll
    for (int j = 0; j < 4; ++j)
        rh[j] = __floats2half2_rn(acc[2*j], acc[2*j+1]);
    xout[o] = res;
}

// ---------------------------------------------------------------------------
// 4) fp16 tensor-core GEMM, M=200000, K=4x64, N=128, block tile 64x128.
//    256 threads = 8 warps (4 m-warps x 2 n-warps), m16n8k16 MMAs.
//    Epilogue stages C in smem, writes coalesced float4 + bias.
// ---------------------------------------------------------------------------
#define ASH 72      // A smem row stride (halfs): 64 + 8 pad
#define WSH 72      // W smem row stride (halfs)
#define CSF 132     // C smem row stride (floats)
#define SMEM_A_BYTES (64 * ASH * 2)            // 9216
#define SMEM_W_BYTES (128 * WSH * 2)           // 18432
#define SMEM_C_BYTES (64 * CSF * 4)            // 33792
#define GEMM_SMEM (SMEM_C_BYTES)               // C region aliases A+W (27648 < 33792)

__device__ __forceinline__ void mma_f16(float c[4],
                                        uint32_t a0, uint32_t a1, uint32_t a2, uint32_t a3,
                                        uint32_t b0, uint32_t b1) {
    asm volatile(
        "mma.sync.aligned.m16n8k16.row.col.f32.f16.f16.f32 "
        "{%0,%1,%2,%3}, {%4,%5,%6,%7}, {%8,%9}, {%0,%1,%2,%3};"
        : "+f"(c[0]), "+f"(c[1]), "+f"(c[2]), "+f"(c[3])
        : "r"(a0), "r"(a1), "r"(a2), "r"(a3), "r"(b0), "r"(b1));
}

__global__ void gemm_kernel(const float* __restrict__ bias,
                            float* __restrict__ out) {
    extern __shared__ char smem_raw[];
    __half* As = (__half*)smem_raw;                     // [64][ASH]
    __half* Wp = (__half*)(smem_raw + SMEM_A_BYTES);    // [128][WSH]
    float*  Cs = (float*)smem_raw;                      // [64][CSF] (aliased)

    int tid  = threadIdx.x;
    int wid  = tid >> 5, lane = tid & 31;
    int wm   = wid & 3;
    int wn   = wid >> 2;
    int m0   = blockIdx.x * 64;
    int g    = lane >> 2;      // 0..7
    int tg   = lane & 3;       // 0..3

    float acc[8][4];
    #pragma unroll
    for (int nt = 0; nt < 8; ++nt)
        #pragma unroll
        for (int j = 0; j < 4; ++j) acc[nt][j] = 0.f;

    for (int p = 0; p < KORD; ++p) {
        // Load A tile: 64 rows x 64 halfs = 512 uint4, 2 per thread
        const __half* Ap = &g_feat[p][0];
        #pragma unroll
        for (int i = 0; i < 2; ++i) {
            int idx  = i * 256 + tid;
            int row  = idx >> 3;
            int col8 = (idx & 7) << 3;
            uint4 t = *(const uint4*)(Ap + (size_t)(m0 + row) * 64 + col8);
            *(uint4*)(As + row * ASH + col8) = t;
        }
        // Load W panel (transposed [o][i]): 128 x 64 halfs = 1024 uint4, 4/thread
        const __half* wp = g_wT + p * (COUT * CIN);
        #pragma unroll
        for (int i = 0; i < 4; ++i) {
            int idx  = i * 256 + tid;
            int o    = idx >> 3;
            int col8 = (idx & 7) << 3;
            uint4 t = *(const uint4*)(wp + o * 64 + col8);
            *(uint4*)(Wp + o * WSH + col8) = t;
        }
        __syncthreads();

        #pragma unroll
        for (int ks = 0; ks < 4; ++ks) {
            int kb = ks * 16;
            const __half* ar  = As + (wm * 16 + g) * ASH + kb + 2 * tg;
            uint32_t a0 = *(const uint32_t*)(ar);
            uint32_t a1 = *(const uint32_t*)(ar + 8 * ASH);
            uint32_t a2 = *(const uint32_t*)(ar + 8);
            uint32_t a3 = *(const uint32_t*)(ar + 8 * ASH + 8);
            #pragma unroll
            for (int nt = 0; nt < 8; ++nt) {
                int cb = wn * 64 + nt * 8;
                const __half* br = Wp + (cb + g) * WSH + kb + 2 * tg;
                uint32_t b0 = *(const uint32_t*)(br);
                uint32_t b1 = *(const uint32_t*)(br + 8);
                mma_f16(acc[nt], a0, a1, a2, a3, b0, b1);
            }
        }
        __syncthreads();
    }

    // Stage C tile into smem (aliases As/Wp — sync above guarantees done)
    {
        int r0 = wm * 16 + g;
        #pragma unroll
        for (int nt = 0; nt < 8; ++nt) {
            int c0 = wn * 64 + nt * 8 + 2 * tg;
            *(float2*)(Cs + r0 * CSF + c0)       = make_float2(acc[nt][0], acc[nt][1]);
            *(float2*)(Cs + (r0 + 8) * CSF + c0) = make_float2(acc[nt][2], acc[nt][3]);
        }
    }
    __syncthreads();

    // Coalesced write-out: out[b][o][v], block covers v in [v0, v0+16)
    int v0 = blockIdx.x * 16;
    #pragma unroll
    for (int i = 0; i < 8; ++i) {
        int idx = i * 256 + tid;       // 0..2047
        int pr  = idx >> 2;            // (b,o) pair
        int q   = idx & 3;             // v quad
        int b   = pr & 3;
        int o   = pr >> 2;
        float bv = __ldg(bias + o);
        float4 t;
        t.x = Cs[(16 * q + 0 * 4 + b) * CSF + o] + bv;
        t.y = Cs[(16 * q + 1 * 4 + b) * CSF + o] + bv;
        t.z = Cs[(16 * q + 2 * 4 + b) * CSF + o] + bv;
        t.w = Cs[(16 * q + 3 * 4 + b) * CSF + o] + bv;
        *(float4*)(out + ((size_t)b * COUT + o) * V + v0 + 4 * q) = t;
    }
}

// ---------------------------------------------------------------------------
extern "C" void kernel_launch(void* const* d_in, const int* in_sizes, int n_in,
                              void* d_out, int out_size) {
    const float* x    = (const float*)d_in[0];
    const int*   rows = (const int*)  d_in[1];
    const int*   cols = (const int*)  d_in[2];
    const float* vals = (const float*)d_in[3];
    const float* w    = (const float*)d_in[4];
    const float* bias = (const float*)d_in[5];
    float*       out  = (float*)d_out;

    (void)in_sizes; (void)n_in; (void)out_size;

    cudaFuncSetAttribute(gemm_kernel,
                         cudaFuncAttributeMaxDynamicSharedMemorySize, GEMM_SMEM);

    transpose_kernel<<<dim3((V + 31) / 32, 256 / 32), dim3(32, 32)>>>(x);
    rowptr_kernel<<<(V + 1 + 255) / 256, 256>>>(rows);
    wconvert_kernel<<<(KORD * COUT * CIN) / 256, 256>>>(w);

    spmm_kernel<<<V / 8, 256>>>(cols, vals, 0, 1, 0, 0);  // x1 = L x0
    spmm_kernel<<<V / 8, 256>>>(cols, vals, 1, 2, 0, 1);  // x2 = 2 L x1 - x0
    spmm_kernel<<<V / 8, 256>>>(cols, vals, 2, 3, 1, 1);  // x3 = 2 L x2 - x1

    gemm_kernel<<<(V * BATCH) / 64, 256, GEMM_SMEM>>>(bias, out);
}

// round 10
// speedup vs baseline: 2.5580x; 1.0879x over previous
#include <cuda_runtime.h>
#include <cuda_fp16.h>
#include <cstdint>

#define V     50000
#define E     800000
#define BATCH 4
#define CIN   64
#define COUT  128
#define KORD  4
#define M_TOT (V * BATCH)          // 200000

// Feature panels: [r = v*4+b][i 0..63] as half  (layout == [v][c=b*64+i])
__device__ __align__(16) __half g_feat[KORD][(size_t)V * BATCH * CIN];
// W transposed to [p][o][i] as half
__device__ __align__(16) __half g_wT[KORD * COUT * CIN];
__device__ int g_rowptr[V + 1];

// ---------------------------------------------------------------------------
// 1) Transpose x (B, Cin, V) -> feat0[v*256 + c] (half)
// ---------------------------------------------------------------------------
__global__ void transpose_kernel(const float* __restrict__ x) {
    __shared__ float tile[32][33];
    int v0 = blockIdx.x * 32;
    int c0 = blockIdx.y * 32;
    int tx = threadIdx.x, ty = threadIdx.y;
    int v = v0 + tx;
    if (v < V) tile[ty][tx] = x[(size_t)(c0 + ty) * V + v];
    __syncthreads();
    int vv = v0 + ty;
    if (vv < V)
        g_feat[0][(size_t)vv * 256 + c0 + tx] = __float2half_rn(tile[tx][ty]);
}

// ---------------------------------------------------------------------------
// 2) row_ptr from sorted COO rows
// ---------------------------------------------------------------------------
__global__ void rowptr_kernel(const int* __restrict__ rows) {
    int r = blockIdx.x * blockDim.x + threadIdx.x;
    if (r > V) return;
    int lo = 0, hi = E;
    while (lo < hi) {
        int mid = (lo + hi) >> 1;
        if (rows[mid] < r) lo = mid + 1; else hi = mid;
    }
    g_rowptr[r] = lo;
}

// ---------------------------------------------------------------------------
// 2b) W (K, Cin, Cout) fp32 -> g_wT (K, Cout, Cin) fp16
// ---------------------------------------------------------------------------
__global__ void wconvert_kernel(const float* __restrict__ w) {
    int n = blockIdx.x * blockDim.x + threadIdx.x;   // < K*COUT*CIN = 32768
    int p = n >> 13;
    int rem = n & 8191;
    int o = rem >> 6;
    int i = rem & 63;
    g_wT[n] = __float2half_rn(w[p * (CIN * COUT) + i * COUT + o]);
}

// ---------------------------------------------------------------------------
// 3) SpMM on fp16 panels (unchanged from round-8 passing version)
// ---------------------------------------------------------------------------
__device__ __forceinline__ void acc_edge(float acc[8], uint4 t, float w) {
    const half2* h = (const half2*)&t;
    #pragma unroll
    for (int j = 0; j < 4; ++j) {
        float2 f = __half22float2(h[j]);
        acc[2*j]   += w * f.x;
        acc[2*j+1] += w * f.y;
    }
}

__global__ void spmm_kernel(const int* __restrict__ cols,
                            const float* __restrict__ vals,
                            int in_idx, int out_idx, int prev_idx, int cheb) {
    int r    = blockIdx.x * 8 + (threadIdx.x >> 5);
    int lane = threadIdx.x & 31;
    const uint4* xin  = (const uint4*)&g_feat[in_idx][0];
    uint4*       xout = (uint4*)&g_feat[out_idx][0];

    int e  = g_rowptr[r];
    int e1 = g_rowptr[r + 1];

    float acc[8];
    #pragma unroll
    for (int j = 0; j < 8; ++j) acc[j] = 0.f;

    while (e + 4 <= e1) {
        int   c0 = __ldg(cols + e),     c1 = __ldg(cols + e + 1);
        int   c2 = __ldg(cols + e + 2), c3 = __ldg(cols + e + 3);
        float w0 = __ldg(vals + e),     w1 = __ldg(vals + e + 1);
        float w2 = __ldg(vals + e + 2), w3 = __ldg(vals + e + 3);
        uint4 t0 = xin[(size_t)c0 * 32 + lane];
        uint4 t1 = xin[(size_t)c1 * 32 + lane];
        uint4 t2 = xin[(size_t)c2 * 32 + lane];
        uint4 t3 = xin[(size_t)c3 * 32 + lane];
        acc_edge(acc, t0, w0);
        acc_edge(acc, t1, w1);
        acc_edge(acc, t2, w2);
        acc_edge(acc, t3, w3);
        e += 4;
    }
    while (e < e1) {
        int   c = __ldg(cols + e);
        float w = __ldg(vals + e);
        uint4 t = xin[(size_t)c * 32 + lane];
        acc_edge(acc, t, w);
        ++e;
    }

    size_t o = (size_t)r * 32 + lane;
    if (cheb) {
        uint4 pv = ((const uint4*)&g_feat[prev_idx][0])[o];
        const half2* h = (const half2*)&pv;
        #pragma unroll
        for (int j = 0; j < 4; ++j) {
            float2 f = __half22float2(h[j]);
            acc[2*j]   = 2.f * acc[2*j]   - f.x;
            acc[2*j+1] = 2.f * acc[2*j+1] - f.y;
        }
    }
    uint4 res;
    half2* rh = (half2*)&res;
    #pragma unroll
    for (int j = 0; j < 4; ++j)
        rh[j] = __floats2half2_rn(acc[2*j], acc[2*j+1]);
    xout[o] = res;
}

// ---------------------------------------------------------------------------
// 4) fp16 tensor-core GEMM, 128x128 block tile, ldmatrix + cp.async pipeline.
//    256 threads = 8 warps (4 m-warps x 2 n-warps); warp tile 32x64.
// ---------------------------------------------------------------------------
#define ASH 72                              // halfs per A smem row (64 + 8 pad)
#define WSH 72                              // halfs per W smem row
#define CSF 132                             // floats per C staging row (EVEN: float2 align)
#define ABUF_BYTES (128 * ASH * 2)          // 18432
#define WBUF_BYTES (128 * WSH * 2)          // 18432
#define GEMM_SMEM  (2 * ABUF_BYTES + 2 * WBUF_BYTES)   // 73728
// C staging (64 rows x CSF floats = 33792 B) aliases the A/W buffers.

__device__ __forceinline__ void mma_f16(float c[4],
                                        uint32_t a0, uint32_t a1, uint32_t a2, uint32_t a3,
                                        uint32_t b0, uint32_t b1) {
    asm volatile(
        "mma.sync.aligned.m16n8k16.row.col.f32.f16.f16.f32 "
        "{%0,%1,%2,%3}, {%4,%5,%6,%7}, {%8,%9}, {%0,%1,%2,%3};"
        : "+f"(c[0]), "+f"(c[1]), "+f"(c[2]), "+f"(c[3])
        : "r"(a0), "r"(a1), "r"(a2), "r"(a3), "r"(b0), "r"(b1));
}

__device__ __forceinline__ void ldsm4(uint32_t f[4], uint32_t addr) {
    asm volatile("ldmatrix.sync.aligned.m8n8.x4.shared.b16 {%0,%1,%2,%3}, [%4];"
                 : "=r"(f[0]), "=r"(f[1]), "=r"(f[2]), "=r"(f[3]) : "r"(addr));
}

__device__ __forceinline__ void cp_async16(uint32_t dst, const void* src) {
    asm volatile("cp.async.cg.shared.global [%0], [%1], 16;" :: "r"(dst), "l"(src));
}
__device__ __forceinline__ void cp_commit() {
    asm volatile("cp.async.commit_group;");
}
template <int N>
__device__ __forceinline__ void cp_wait() {
    asm volatile("cp.async.wait_group %0;" :: "n"(N));
}

__global__ __launch_bounds__(256, 2)
void gemm_kernel(const float* __restrict__ bias, float* __restrict__ out) {
    extern __shared__ char smem_raw[];
    uint32_t smem_u32 = (uint32_t)__cvta_generic_to_shared(smem_raw);
    float* Cs = (float*)smem_raw;   // aliased staging, [64][CSF]

    int tid  = threadIdx.x;
    int wid  = tid >> 5, lane = tid & 31;
    int wm   = wid & 3;        // m-warp: rows wm*32 .. wm*32+31
    int wn   = wid >> 2;       // n-warp: cols wn*64 .. wn*64+63
    int m0   = blockIdx.x * 128;
    int g    = lane >> 2;      // 0..7
    int tg   = lane & 3;       // 0..3
    int lq   = lane & 15;      // ldmatrix row-select
    int lh   = (lane >> 4) << 3;

    // smem buffer base offsets (bytes)
    uint32_t aoff[2] = { smem_u32,                smem_u32 + ABUF_BYTES };
    uint32_t woff[2] = { smem_u32 + 2*ABUF_BYTES, smem_u32 + 2*ABUF_BYTES + WBUF_BYTES };

    float acc[2][8][4];
    #pragma unroll
    for (int mt = 0; mt < 2; ++mt)
        #pragma unroll
        for (int nt = 0; nt < 8; ++nt)
            #pragma unroll
            for (int j = 0; j < 4; ++j) acc[mt][nt][j] = 0.f;

    // prefetch helper: panel p into buffer buf
    auto prefetch = [&](int p, int buf) {
        const __half* Ap = &g_feat[p][0];
        #pragma unroll
        for (int i = 0; i < 4; ++i) {
            int idx  = i * 256 + tid;          // 0..1023
            int row  = idx >> 3;               // 0..127
            int col8 = (idx & 7) << 3;
            int rg   = m0 + row; if (rg > M_TOT - 1) rg = M_TOT - 1;
            cp_async16(aoff[buf] + (uint32_t)(row * ASH + col8) * 2,
                       Ap + (size_t)rg * 64 + col8);
        }
        const __half* wp = g_wT + p * (COUT * CIN);
        #pragma unroll
        for (int i = 0; i < 4; ++i) {
            int idx  = i * 256 + tid;
            int o    = idx >> 3;
            int col8 = (idx & 7) << 3;
            cp_async16(woff[buf] + (uint32_t)(o * WSH + col8) * 2,
                       wp + o * 64 + col8);
        }
        cp_commit();
    };

    prefetch(0, 0);

    for (int p = 0; p < KORD; ++p) {
        int cur = p & 1;
        if (p < KORD - 1) prefetch(p + 1, cur ^ 1);
        if (p < KORD - 1) cp_wait<1>(); else cp_wait<0>();
        __syncthreads();

        uint32_t abase = aoff[cur];
        uint32_t wbase = woff[cur];
        #pragma unroll
        for (int ks = 0; ks < 4; ++ks) {
            int kb = ks * 16;
            uint32_t afr[2][4];
            #pragma unroll
            for (int mt = 0; mt < 2; ++mt)
                ldsm4(afr[mt], abase + (uint32_t)((wm*32 + mt*16 + lq) * ASH + kb + lh) * 2);
            uint32_t bfr[4][4];
            #pragma unroll
            for (int bp = 0; bp < 4; ++bp)
                ldsm4(bfr[bp], wbase + (uint32_t)((wn*64 + bp*16 + lq) * WSH + kb + lh) * 2);
            #pragma unroll
            for (int mt = 0; mt < 2; ++mt)
                #pragma unroll
                for (int bp = 0; bp < 4; ++bp) {
                    mma_f16(acc[mt][2*bp],   afr[mt][0], afr[mt][1], afr[mt][2], afr[mt][3],
                            bfr[bp][0], bfr[bp][2]);
                    mma_f16(acc[mt][2*bp+1], afr[mt][0], afr[mt][1], afr[mt][2], afr[mt][3],
                            bfr[bp][1], bfr[bp][3]);
                }
        }
        __syncthreads();
    }

    // Epilogue: two 64-row chunks, staged via smem (aliases A/W buffers).
    #pragma unroll
    for (int ch = 0; ch < 2; ++ch) {
        __syncthreads();
        if ((wm >> 1) == ch) {
            int rbase = (wm & 1) * 32;
            #pragma unroll
            for (int mt = 0; mt < 2; ++mt) {
                int rl = rbase + mt * 16 + g;
                #pragma unroll
                for (int nt = 0; nt < 8; ++nt) {
                    int c0 = wn * 64 + nt * 8 + 2 * tg;
                    *(float2*)(Cs + rl * CSF + c0)       = make_float2(acc[mt][nt][0], acc[mt][nt][1]);
                    *(float2*)(Cs + (rl + 8) * CSF + c0) = make_float2(acc[mt][nt][2], acc[mt][nt][3]);
                }
            }
        }
        __syncthreads();

        int vbase = blockIdx.x * 32 + ch * 16;
        #pragma unroll
        for (int i = 0; i < 8; ++i) {
            int idx = i * 256 + tid;       // 0..2047
            int pr  = idx >> 2;            // (b,o) pair
            int q   = idx & 3;             // v quad
            int b   = pr & 3;
            int o   = pr >> 2;
            int v   = vbase + 4 * q;
            if (v < V) {
                float bv = __ldg(bias + o);
                float4 t;
                t.x = Cs[(16 * q + 0 * 4 + b) * CSF + o] + bv;
                t.y = Cs[(16 * q + 1 * 4 + b) * CSF + o] + bv;
                t.z = Cs[(16 * q + 2 * 4 + b) * CSF + o] + bv;
                t.w = Cs[(16 * q + 3 * 4 + b) * CSF + o] + bv;
                *(float4*)(out + ((size_t)b * COUT + o) * V + v) = t;
            }
        }
    }
}

// ---------------------------------------------------------------------------
extern "C" void kernel_launch(void* const* d_in, const int* in_sizes, int n_in,
                              void* d_out, int out_size) {
    const float* x    = (const float*)d_in[0];
    const int*   rows = (const int*)  d_in[1];
    const int*   cols = (const int*)  d_in[2];
    const float* vals = (const float*)d_in[3];
    const float* w    = (const float*)d_in[4];
    const float* bias = (const float*)d_in[5];
    float*       out  = (float*)d_out;

    (void)in_sizes; (void)n_in; (void)out_size;

    cudaFuncSetAttribute(gemm_kernel,
                         cudaFuncAttributeMaxDynamicSharedMemorySize, GEMM_SMEM);

    transpose_kernel<<<dim3((V + 31) / 32, 256 / 32), dim3(32, 32)>>>(x);
    rowptr_kernel<<<(V + 1 + 255) / 256, 256>>>(rows);
    wconvert_kernel<<<(KORD * COUT * CIN) / 256, 256>>>(w);

    spmm_kernel<<<V / 8, 256>>>(cols, vals, 0, 1, 0, 0);  // x1 = L x0
    spmm_kernel<<<V / 8, 256>>>(cols, vals, 1, 2, 0, 1);  // x2 = 2 L x1 - x0
    spmm_kernel<<<V / 8, 256>>>(cols, vals, 2, 3, 1, 1);  // x3 = 2 L x2 - x1

    // 200000 rows / 128 per block = 1562.5 -> 1563 blocks (last clamped)
    gemm_kernel<<<(M_TOT + 127) / 128, 256, GEMM_SMEM>>>(bias, out);
}